// round 1
// baseline (speedup 1.0000x reference)
#include <cuda_runtime.h>
#include <math.h>

#define HW 65536            // 256*256
#define NPIX 256

// ---------------- scratch (device globals; no allocation allowed) -------------
__device__ float  g_pooled[2*192*1024];
__device__ float4 g_params[2*6*1024];          // {sx, sy, px, py} per (b,head,wy,wx)
__device__ float  g_q    [2*192*HW];
__device__ float  g_qpan [2*192*HW];
__device__ float  g_k    [2*192*HW];
__device__ float  g_v    [2*192*HW];
__device__ float  g_attn [2*192*HW];
__device__ float  g_attnp[2*192*HW];

// ---------------- 1) 8x8 window mean + leaky --------------------------------
__global__ void __launch_bounds__(256) pool_kernel(const float* __restrict__ x) {
    int idx = blockIdx.x * 256 + threadIdx.x;
    if (idx >= 2*192*1024) return;
    int wx = idx & 31, wy = (idx >> 5) & 31;
    int c  = (idx >> 10) % 192, b = idx / (192*1024);
    const float* p = x + ((b*192 + c)*256 + wy*8)*256 + wx*8;
    float s = 0.f;
    #pragma unroll
    for (int i = 0; i < 8; i++) {
        #pragma unroll
        for (int j = 0; j < 8; j++) s += p[i*256 + j];
    }
    s *= (1.0f/64.0f);
    g_pooled[idx] = (s >= 0.f) ? s : 0.01f*s;
}

// ---------------- 2) per-window offset/scale params --------------------------
__global__ void params_kernel(const float* __restrict__ off_w, const float* __restrict__ off_b,
                              const float* __restrict__ sc_w,  const float* __restrict__ sc_b) {
    int idx = blockIdx.x * blockDim.x + threadIdx.x;
    if (idx >= 2*6*1024) return;
    int wx = idx & 31, wy = (idx >> 5) & 31;
    int h  = (idx >> 10) % 6, b = idx / (6*1024);
    const float* pv = g_pooled + b*192*1024 + wy*32 + wx;
    float ox = off_b[h*2], oy = off_b[h*2+1];
    float sx = sc_b[h*2],  sy = sc_b[h*2+1];
    const float* owx = off_w + (h*2)*192; const float* owy = owx + 192;
    const float* swx = sc_w  + (h*2)*192; const float* swy = swx + 192;
    for (int c = 0; c < 192; c++) {
        float p = pv[c*1024];
        ox += owx[c]*p; oy += owy[c]*p;
        sx += swx[c]*p; sy += swy[c]*p;
    }
    // pixel-space: gx = wx*8+j + (j-3.5)*sx + ox*(255/64)*0.5*... -> ox*(127.5/32)
    float4 r; r.x = sx; r.y = sy; r.z = ox*(127.5f/32.0f); r.w = oy*(127.5f/32.0f);
    g_params[idx] = r;
}

// ---------------- 3) qkv GEMM: C[M,65536] = W[M,192] * X[192,65536] ----------
// mode 0: M=576, route o/192 -> {g_qpan, g_k, g_v}.  mode 1: M=192 -> g_q.
__global__ void __launch_bounds__(256) qkv_gemm(const float* __restrict__ X,
                                                const float* __restrict__ W,
                                                const float* __restrict__ bias, int mode) {
    __shared__ float As[16][64];
    __shared__ float Bs[16][64];
    int n0 = blockIdx.x * 64, m0 = blockIdx.y * 64, b = blockIdx.z;
    const float* Xb = X + b*192*HW;
    int tid = threadIdx.x;
    int tx = tid & 15, ty = tid >> 4;
    int lak = (tid*4) & 15, lam = (tid*4) >> 4;        // A load: 4 consecutive k
    int lbn = (tid*4) & 63, lbk = (tid*4) >> 6;        // B load: float4 along n
    float acc[4][4] = {};
    for (int kk = 0; kk < 192; kk += 16) {
        float4 wa = *(const float4*)(W + (m0 + lam)*192 + kk + lak);
        As[lak+0][lam] = wa.x; As[lak+1][lam] = wa.y;
        As[lak+2][lam] = wa.z; As[lak+3][lam] = wa.w;
        float4 xb = *(const float4*)(Xb + (kk + lbk)*HW + n0 + lbn);
        Bs[lbk][lbn+0] = xb.x; Bs[lbk][lbn+1] = xb.y;
        Bs[lbk][lbn+2] = xb.z; Bs[lbk][lbn+3] = xb.w;
        __syncthreads();
        #pragma unroll
        for (int k = 0; k < 16; k++) {
            float a[4], bv[4];
            #pragma unroll
            for (int u = 0; u < 4; u++) a[u]  = As[k][ty*4 + u];
            #pragma unroll
            for (int u = 0; u < 4; u++) bv[u] = Bs[k][tx*4 + u];
            #pragma unroll
            for (int u = 0; u < 4; u++)
                #pragma unroll
                for (int w2 = 0; w2 < 4; w2++) acc[u][w2] += a[u]*bv[w2];
        }
        __syncthreads();
    }
    #pragma unroll
    for (int i = 0; i < 4; i++) {
        int m = m0 + ty*4 + i;
        float bi = bias[m];
        int which = m / 192, c = m - which*192;
        float* dst;
        if (mode == 1) dst = g_q;
        else dst = (which == 0) ? g_qpan : ((which == 1) ? g_k : g_v);
        float4 o;
        o.x = acc[i][0] + bi; o.y = acc[i][1] + bi;
        o.z = acc[i][2] + bi; o.w = acc[i][3] + bi;
        *(float4*)(dst + (b*192 + c)*HW + n0 + tx*4) = o;
    }
}

// ---------------- 4) fused grid-sample + window attention --------------------
// block = one (b, wy, wx, head); threads 0-63: q stream, 64-127: q_pan stream.
__global__ void __launch_bounds__(128) attn_kernel(const float* __restrict__ rpb_table) {
    __shared__ float ksm[64*32];
    __shared__ float vsm[64*32];
    __shared__ float rpbsm[64*64];
    __shared__ float gxs[64], gys[64];
    int bx = blockIdx.x;
    int h = bx % 6; int t = bx / 6;
    int wx = t & 31, wy = (t >> 5) & 31, b = t >> 10;
    int tid = threadIdx.x;

    if (tid < 64) {
        int i = tid >> 3, j = tid & 7;
        float4 p = g_params[((b*6 + h)*32 + wy)*32 + wx];
        gxs[tid] = (float)(wx*8 + j) + ((float)j - 3.5f)*p.x + p.z;
        gys[tid] = (float)(wy*8 + i) + ((float)i - 3.5f)*p.y + p.w;
    }
    for (int idx = tid; idx < 4096; idx += 128) {
        int q = idx >> 6, k2 = idx & 63;
        int rpi = ((q >> 3) - (k2 >> 3) + 7)*15 + ((q & 7) - (k2 & 7) + 7);
        rpbsm[idx] = rpb_table[rpi*6 + h];
    }
    __syncthreads();

    int cbase = (b*192 + h*32)*HW;
    const float* kb = g_k + cbase;
    const float* vb = g_v + cbase;
    for (int idx = tid; idx < 2048; idx += 128) {
        int pos = idx >> 5, d = idx & 31;
        float gx = gxs[pos], gy = gys[pos];
        float xf = floorf(gx), yf = floorf(gy);
        int x0 = (int)xf, y0 = (int)yf;
        float fx = gx - xf, fy = gy - yf;
        int off = d*HW;
        float kacc = 0.f, vacc = 0.f;
        bool vx0 = (x0 >= 0) & (x0 < NPIX), vx1 = (x0+1 >= 0) & (x0+1 < NPIX);
        bool vy0 = (y0 >= 0) & (y0 < NPIX), vy1 = (y0+1 >= 0) & (y0+1 < NPIX);
        if (vx0 & vy0) { float w = (1.f-fx)*(1.f-fy); int o = off + y0*256 + x0;       kacc += w*kb[o]; vacc += w*vb[o]; }
        if (vx1 & vy0) { float w = fx*(1.f-fy);       int o = off + y0*256 + x0+1;     kacc += w*kb[o]; vacc += w*vb[o]; }
        if (vx0 & vy1) { float w = (1.f-fx)*fy;       int o = off + (y0+1)*256 + x0;   kacc += w*kb[o]; vacc += w*vb[o]; }
        if (vx1 & vy1) { float w = fx*fy;             int o = off + (y0+1)*256 + x0+1; kacc += w*kb[o]; vacc += w*vb[o]; }
        ksm[pos*32 + d] = kacc;
        vsm[pos*32 + d] = vacc;
    }
    __syncthreads();

    int qi = tid & 63;
    const float* qb = ((tid < 64) ? g_q : g_qpan) + cbase;
    int i = qi >> 3, j = qi & 7;
    int pix = (wy*8 + i)*256 + wx*8 + j;
    float qr[32];
    #pragma unroll
    for (int d = 0; d < 32; d++) qr[d] = qb[d*HW + pix] * 0.17677669529663687f;

    float sc[64];
    float mx = -1e30f;
    #pragma unroll
    for (int k = 0; k < 64; k++) {
        float s = 0.f;
        #pragma unroll
        for (int d = 0; d < 32; d++) s += qr[d]*ksm[k*32 + d];
        s += rpbsm[qi*64 + k];
        sc[k] = s;
        mx = fmaxf(mx, s);
    }
    float sum = 0.f;
    #pragma unroll
    for (int k = 0; k < 64; k++) { float e = expf(sc[k] - mx); sc[k] = e; sum += e; }
    float inv = 1.0f/sum;
    float ov[32] = {};
    #pragma unroll
    for (int k = 0; k < 64; k++) {
        float a = sc[k]*inv;
        #pragma unroll
        for (int d = 0; d < 32; d++) ov[d] += a*vsm[k*32 + d];
    }
    float* dst = ((tid < 64) ? g_attn : g_attnp) + cbase;
    #pragma unroll
    for (int d = 0; d < 32; d++) dst[d*HW + pix] = ov[d];
}

// ---------------- 5) proj GEMM: out = proj_w * attn + b ----------------------
__global__ void __launch_bounds__(256) proj_gemm(const float* __restrict__ W,
                                                 const float* __restrict__ bias,
                                                 float* __restrict__ out) {
    __shared__ float As[16][64];
    __shared__ float Bs[16][64];
    int z = blockIdx.z; int b = z & 1; int strm = z >> 1;
    const float* Xb = (strm ? g_attnp : g_attn) + b*192*HW;
    float* dstb = out + strm*(2*192*HW) + b*192*HW;
    int n0 = blockIdx.x * 64, m0 = blockIdx.y * 64;
    int tid = threadIdx.x;
    int tx = tid & 15, ty = tid >> 4;
    int lak = (tid*4) & 15, lam = (tid*4) >> 4;
    int lbn = (tid*4) & 63, lbk = (tid*4) >> 6;
    float acc[4][4] = {};
    for (int kk = 0; kk < 192; kk += 16) {
        float4 wa = *(const float4*)(W + (m0 + lam)*192 + kk + lak);
        As[lak+0][lam] = wa.x; As[lak+1][lam] = wa.y;
        As[lak+2][lam] = wa.z; As[lak+3][lam] = wa.w;
        float4 xb = *(const float4*)(Xb + (kk + lbk)*HW + n0 + lbn);
        Bs[lbk][lbn+0] = xb.x; Bs[lbk][lbn+1] = xb.y;
        Bs[lbk][lbn+2] = xb.z; Bs[lbk][lbn+3] = xb.w;
        __syncthreads();
        #pragma unroll
        for (int k = 0; k < 16; k++) {
            float a[4], bv[4];
            #pragma unroll
            for (int u = 0; u < 4; u++) a[u]  = As[k][ty*4 + u];
            #pragma unroll
            for (int u = 0; u < 4; u++) bv[u] = Bs[k][tx*4 + u];
            #pragma unroll
            for (int u = 0; u < 4; u++)
                #pragma unroll
                for (int w2 = 0; w2 < 4; w2++) acc[u][w2] += a[u]*bv[w2];
        }
        __syncthreads();
    }
    #pragma unroll
    for (int i = 0; i < 4; i++) {
        int m = m0 + ty*4 + i;
        float bi = bias[m];
        float4 o;
        o.x = acc[i][0] + bi; o.y = acc[i][1] + bi;
        o.z = acc[i][2] + bi; o.w = acc[i][3] + bi;
        *(float4*)(dstb + m*HW + n0 + tx*4) = o;
    }
}

// ---------------- launch ----------------------------------------------------
extern "C" void kernel_launch(void* const* d_in, const int* in_sizes, int n_in,
                              void* d_out, int out_size) {
    const float* x      = (const float*)d_in[0];
    const float* lms    = (const float*)d_in[1];
    const float* qkv_w  = (const float*)d_in[2];
    const float* qkv_b  = (const float*)d_in[3];
    const float* off_w  = (const float*)d_in[4];
    const float* off_b  = (const float*)d_in[5];
    const float* sc_w   = (const float*)d_in[6];
    const float* sc_b   = (const float*)d_in[7];
    const float* proj_w = (const float*)d_in[8];
    const float* proj_b = (const float*)d_in[9];
    const float* rpb    = (const float*)d_in[10];
    float* out = (float*)d_out;

    pool_kernel<<<(2*192*1024 + 255)/256, 256>>>(x);
    params_kernel<<<(2*6*1024 + 255)/256, 256>>>(off_w, off_b, sc_w, sc_b);
    qkv_gemm<<<dim3(1024, 9, 2), 256>>>(x,   qkv_w, qkv_b, 0);
    qkv_gemm<<<dim3(1024, 3, 2), 256>>>(lms, qkv_w, qkv_b, 1);
    attn_kernel<<<2*32*32*6, 128>>>(rpb);
    proj_gemm<<<dim3(1024, 3, 4), 256>>>(proj_w, proj_b, out);
}